// round 9
// baseline (speedup 1.0000x reference)
#include <cuda_runtime.h>
#include <cuda_bf16.h>
#include <math.h>

// Problem constants (fixed shapes)
#define NN      4096      // nodes
#define KIN     1433      // in features
#define NH      8         // heads
#define FOUT    64        // NH*DHD
#define LRELU   0.2f

// Attention tiling (tensor-core version)
#define TIA     64        // i rows per block
#define TJ      64        // j tile in smem
#define SPLITS  16        // j-axis splits
#define CHUNK   (NN / SPLITS)   // 256

// GEMM split-K (128x64 tiles, 128 threads, 8x8 per thread)
#define GM      128
#define KSPL    16
#define KCH     90        // ceil(1433/16)

typedef unsigned long long u64;

// ---------------- scratch (no allocations allowed) ----------------
__device__ __align__(16) float g_buf[NN * FOUT];             // 1 MB
__device__ __align__(16) float2 Lbuf[NN * NH];               // (e^sl, e^{0.2 sl}) packed pair
__device__ __align__(16) float2 Rbuf[NN * NH];               // (e^sr, e^{0.2 sr}) packed pair
__device__ __align__(16) float pacc_buf[SPLITS * NN * FOUT]; // 16 MB (gemm partials then attn partials)
__device__ __align__(16) float psum_buf[SPLITS * NN * NH];   // 2 MB partial denom

// f32x2 packed helpers (Blackwell; PTX-only). "l" constraint = 64-bit int reg.
__device__ __forceinline__ u64 ffma2(u64 a, u64 b, u64 c) {
    u64 d;
    asm("fma.rn.f32x2 %0, %1, %2, %3;" : "=l"(d) : "l"(a), "l"(b), "l"(c));
    return d;
}
__device__ __forceinline__ u64 fmul2(u64 a, u64 b) {
    u64 d;
    asm("mul.rn.f32x2 %0, %1, %2;" : "=l"(d) : "l"(a), "l"(b));
    return d;
}
__device__ __forceinline__ u64 pack2(float lo, float hi) {
    u64 d;
    asm("mov.b64 %0, {%1, %2};" : "=l"(d) : "f"(lo), "f"(hi));
    return d;
}
__device__ __forceinline__ void unpack2(u64 d, float& lo, float& hi) {
    asm("mov.b64 {%0, %1}, %2;" : "=f"(lo), "=f"(hi) : "l"(d));
}
__device__ __forceinline__ unsigned int tf32_rna(float f) {
    unsigned int r;
    asm("cvt.rna.tf32.f32 %0, %1;" : "=r"(r) : "f"(f));
    return r;
}
// w = tf32-rounded((max of both lrelu branches) bit-masked by mu). The rna rounding
// makes the FADD denominator and the mma numerator use bit-identical weights.
__device__ __forceinline__ float wmax(u64 eifi, u64 ef, unsigned int mu) {
    const u64 p = fmul2(eifi, ef);
    float lo, hi; unpack2(p, lo, hi);
    const float mx = fmaxf(lo, hi);                                   // FMNMX (alu)
    const float wm = __uint_as_float(__float_as_uint(mx) & mu);       // LOP3 (alu)
    return __uint_as_float(tf32_rna(wm));                             // CVT (exact in mma)
}
// tf32 mma: D += A(16x8) * B(8x8), A values already tf32-representable
__device__ __forceinline__ void mma_tf32(float* d, float a0, float a1, float a2, float a3,
                                         unsigned int b0, unsigned int b1) {
    asm volatile(
        "mma.sync.aligned.m16n8k8.row.col.f32.tf32.tf32.f32 "
        "{%0,%1,%2,%3}, {%4,%5,%6,%7}, {%8,%9}, {%0,%1,%2,%3};"
        : "+f"(d[0]), "+f"(d[1]), "+f"(d[2]), "+f"(d[3])
        : "r"(__float_as_uint(a0)), "r"(__float_as_uint(a1)),
          "r"(__float_as_uint(a2)), "r"(__float_as_uint(a3)),
          "r"(b0), "r"(b1));
}

// ---------------- Kernel 1: g = vert @ W  (f32x2 GEMM, split-K, 8x8/thread) ----------------
__global__ void __launch_bounds__(128) gemm_proj(const float* __restrict__ A,
                                                 const float* __restrict__ B)
{
    __shared__ u64   Asd[16][132];  // (a,a) dup pairs; EVEN stride -> 16B-aligned rows
    __shared__ float Bs[16][68];
    const int tid = threadIdx.x;
    const int m0  = blockIdx.x * GM;
    const int spl = blockIdx.y;
    const int kb  = spl * KCH;
    const int ke  = min(KIN, kb + KCH);
    const int tx  = tid & 7;
    const int ty  = tid >> 3;

    u64 acc[8][4] = {};

    for (int k0 = kb; k0 < ke; k0 += 16) {
        {
            const int kk  = tid & 15;
            const int rb  = tid >> 4;
            const bool ok = (k0 + kk < ke);
            #pragma unroll
            for (int p = 0; p < 16; p++) {
                const int row = rb + p * 8;
                const float v = ok ? A[(size_t)(m0 + row) * KIN + k0 + kk] : 0.f;
                Asd[kk][row] = pack2(v, v);
            }
        }
        {
            #pragma unroll
            for (int p = 0; p < 2; p++) {
                const int i4 = tid + p * 128;
                const int rr = i4 >> 4;
                const int c4 = i4 & 15;
                float4 v = make_float4(0.f, 0.f, 0.f, 0.f);
                if (k0 + rr < ke) v = *(const float4*)&B[(size_t)(k0 + rr) * 64 + c4 * 4];
                *(float4*)&Bs[rr][c4 * 4] = v;
            }
        }
        __syncthreads();

        #pragma unroll
        for (int kk = 0; kk < 16; kk++) {
            ulonglong2 a01 = *(const ulonglong2*)&Asd[kk][ty * 8 + 0];
            ulonglong2 a23 = *(const ulonglong2*)&Asd[kk][ty * 8 + 2];
            ulonglong2 a45 = *(const ulonglong2*)&Asd[kk][ty * 8 + 4];
            ulonglong2 a67 = *(const ulonglong2*)&Asd[kk][ty * 8 + 6];
            ulonglong2 b01 = *(const ulonglong2*)&Bs[kk][tx * 8 + 0];
            ulonglong2 b23 = *(const ulonglong2*)&Bs[kk][tx * 8 + 4];
            u64 ar[8] = {a01.x, a01.y, a23.x, a23.y, a45.x, a45.y, a67.x, a67.y};
            #pragma unroll
            for (int r = 0; r < 8; r++) {
                acc[r][0] = ffma2(ar[r], b01.x, acc[r][0]);
                acc[r][1] = ffma2(ar[r], b01.y, acc[r][1]);
                acc[r][2] = ffma2(ar[r], b23.x, acc[r][2]);
                acc[r][3] = ffma2(ar[r], b23.y, acc[r][3]);
            }
        }
        __syncthreads();
    }

    #pragma unroll
    for (int r = 0; r < 8; r++) {
        float x0, x1, x2, x3, x4, x5, x6, x7;
        unpack2(acc[r][0], x0, x1);
        unpack2(acc[r][1], x2, x3);
        unpack2(acc[r][2], x4, x5);
        unpack2(acc[r][3], x6, x7);
        float* p = &pacc_buf[((size_t)spl * NN + m0 + ty * 8 + r) * 64 + tx * 8];
        *(float4*)(p + 0) = make_float4(x0, x1, x2, x3);
        *(float4*)(p + 4) = make_float4(x4, x5, x6, x7);
    }
}

// ---------------- Kernel 2: reduce split-K + per-(node,head) factored exps ----------------
__global__ void __launch_bounds__(256) prep_scores(const float* __restrict__ a_l,
                                                   const float* __restrict__ a_r)
{
    const int t = blockIdx.x * blockDim.x + threadIdx.x;
    const int n = t >> 3;
    const int h = t & 7;

    float4 s0 = make_float4(0.f, 0.f, 0.f, 0.f);
    float4 s1 = s0;
    #pragma unroll
    for (int s = 0; s < KSPL; s++) {
        const float* p = &pacc_buf[((size_t)s * NN + n) * 64 + h * 8];
        const float4 p0 = *(const float4*)(p + 0);
        const float4 p1 = *(const float4*)(p + 4);
        s0.x += p0.x; s0.y += p0.y; s0.z += p0.z; s0.w += p0.w;
        s1.x += p1.x; s1.y += p1.y; s1.z += p1.z; s1.w += p1.w;
    }
    *(float4*)&g_buf[(size_t)n * 64 + h * 8 + 0] = s0;
    *(float4*)&g_buf[(size_t)n * 64 + h * 8 + 4] = s1;

    const float4 al0 = *(const float4*)&a_l[h * 8 + 0];
    const float4 al1 = *(const float4*)&a_l[h * 8 + 4];
    const float4 ar0 = *(const float4*)&a_r[h * 8 + 0];
    const float4 ar1 = *(const float4*)&a_r[h * 8 + 4];

    const float sl = s0.x*al0.x + s0.y*al0.y + s0.z*al0.z + s0.w*al0.w
                   + s1.x*al1.x + s1.y*al1.y + s1.z*al1.z + s1.w*al1.w;
    const float sr = s0.x*ar0.x + s0.y*ar0.y + s0.z*ar0.z + s0.w*ar0.w
                   + s1.x*ar1.x + s1.y*ar1.y + s1.z*ar1.z + s1.w*ar1.w;

    Lbuf[t] = make_float2(expf(sl), expf(LRELU * sl));
    Rbuf[t] = make_float2(expf(sr), expf(LRELU * sr));
}

// ---------------- Kernel 3: masked softmax-aggregation via tf32 mma ----------------
// 512 threads = 16 warps; warp = 16 rows x 2 heads (low register pressure, 32 warps/SM).
__global__ void __launch_bounds__(512, 2) attn_kernel(const int* __restrict__ edge)
{
    __shared__ u64 gp[8][64][4];           // 16 KB: (tf32 G[j4], tf32 G[j4+4]) pairs
    __shared__ u64 rsu[TJ * 8];            // 4 KB: (e^sr, e^{.2 sr}) per (j,h)
    __shared__ unsigned int msk[TIA][68];  // 17 KB: 0xFFFFFFFF/0 per (i,j)

    const int tid  = threadIdx.x;
    const int lane = tid & 31;
    const int wrp  = tid >> 5;      // 0..15
    const int gid  = lane >> 2;     // fragment row 0..7
    const int tig  = lane & 3;      // fragment col/k group
    const int rw   = (wrp & 3) * 16;
    const int hb   = (wrp >> 2) * 2;    // head pair base (0,2,4,6)
    const int split = blockIdx.x;
    const int i0   = blockIdx.y * TIA;
    const int j0   = split * CHUNK;

    const u64* Lu = (const u64*)Lbuf;
    const u64* Ru = (const u64*)Rbuf;

    u64 EiF[2][2];
    #pragma unroll
    for (int hh = 0; hh < 2; hh++) {
        EiF[hh][0] = Lu[(size_t)(i0 + rw + gid) * 8 + hb + hh];
        EiF[hh][1] = Lu[(size_t)(i0 + rw + gid + 8) * 8 + hb + hh];
    }

    float accG[2][4] = {};           // O fragments per head
    float sL0[2] = {}, sL1[2] = {};  // denominator partial sums (rows gid, gid+8)

    const int4* e4 = (const int4*)edge;

    for (int jt = 0; jt < CHUNK; jt += TJ) {
        const int jb = j0 + jt;
        __syncthreads();

        // stage G pairs (rna tf32): 2048 u64 -> 4 per thread
        #pragma unroll
        for (int k = 0; k < 4; k++) {
            const int idx = tid + k * 512;
            const int hd  = (idx >> 2) & 63;
            const int j4  = idx & 3;
            const int j8  = idx >> 8;
            const int jr  = jb + j8 * 8 + j4;
            const unsigned int lo = tf32_rna(g_buf[(size_t)jr * 64 + hd]);
            const unsigned int hi = tf32_rna(g_buf[(size_t)(jr + 4) * 64 + hd]);
            gp[j8][hd][j4] = ((u64)hi << 32) | lo;
        }
        // stage EF: 512 u64 -> 1 per thread
        rsu[tid] = Ru[(size_t)(jb + (tid >> 3)) * 8 + (tid & 7)];
        // stage mask words: 1024 int4 -> 2 per thread
        #pragma unroll
        for (int k = 0; k < 2; k++) {
            const int idx = tid + k * 512;
            const int ii  = idx >> 4;
            const int jq  = idx & 15;
            const int4 v  = e4[(size_t)(i0 + ii) * (NN / 4) + (jb >> 2) + jq];
            uint4 f;
            f.x = (v.x != 0) ? 0xFFFFFFFFu : 0u;
            f.y = (v.y != 0) ? 0xFFFFFFFFu : 0u;
            f.z = (v.z != 0) ? 0xFFFFFFFFu : 0u;
            f.w = (v.w != 0) ? 0xFFFFFFFFu : 0u;
            *(uint4*)&msk[ii][jq * 4] = f;
        }
        __syncthreads();

        #pragma unroll 2
        for (int j8 = 0; j8 < 8; j8++) {
            const unsigned int mu0 = msk[rw + gid][j8 * 8 + tig];
            const unsigned int mu1 = msk[rw + gid + 8][j8 * 8 + tig];
            const unsigned int mu2 = msk[rw + gid][j8 * 8 + tig + 4];
            const unsigned int mu3 = msk[rw + gid + 8][j8 * 8 + tig + 4];
            // EF for head pair hb, hb+1 (adjacent u64s, 16B-aligned since hb even)
            const ulonglong2 e0 = *(const ulonglong2*)&rsu[(j8 * 8 + tig) * 8 + hb];
            const ulonglong2 e1 = *(const ulonglong2*)&rsu[(j8 * 8 + tig + 4) * 8 + hb];
            const u64 EF0[2] = {e0.x, e0.y};
            const u64 EF1[2] = {e1.x, e1.y};
            #pragma unroll
            for (int hh = 0; hh < 2; hh++) {
                const int h = hb + hh;
                const float a0 = wmax(EiF[hh][0], EF0[hh], mu0);
                const float a1 = wmax(EiF[hh][1], EF0[hh], mu1);
                const float a2 = wmax(EiF[hh][0], EF1[hh], mu2);
                const float a3 = wmax(EiF[hh][1], EF1[hh], mu3);
                sL0[hh] += a0 + a2;
                sL1[hh] += a1 + a3;
                const uint2 b = *(const uint2*)&gp[j8][h * 8 + gid][tig];
                mma_tf32(accG[hh], a0, a1, a2, a3, b.x, b.y);
            }
        }
    }

    // epilogue: reduce denominators over the 4-lane tig group, write partials
    #pragma unroll
    for (int hh = 0; hh < 2; hh++) {
        float s0 = sL0[hh], s1 = sL1[hh];
        s0 += __shfl_xor_sync(0xFFFFFFFFu, s0, 1);
        s0 += __shfl_xor_sync(0xFFFFFFFFu, s0, 2);
        s1 += __shfl_xor_sync(0xFFFFFFFFu, s1, 1);
        s1 += __shfl_xor_sync(0xFFFFFFFFu, s1, 2);

        const int h = hb + hh;
        const int ir0 = i0 + rw + gid;
        const int ir1 = ir0 + 8;
        float* p0 = &pacc_buf[((size_t)split * NN + ir0) * 64 + h * 8 + tig * 2];
        float* p1 = &pacc_buf[((size_t)split * NN + ir1) * 64 + h * 8 + tig * 2];
        *(float2*)p0 = make_float2(accG[hh][0], accG[hh][1]);
        *(float2*)p1 = make_float2(accG[hh][2], accG[hh][3]);
        if (tig == 0) {
            psum_buf[((size_t)split * NN + ir0) * 8 + h] = s0;
            psum_buf[((size_t)split * NN + ir1) * 8 + h] = s1;
        }
    }
}

// ---------------- Kernel 4: combine splits, normalize, ELU ----------------
__global__ void __launch_bounds__(256) combine_kernel(float* __restrict__ out)
{
    const int t = blockIdx.x * blockDim.x + threadIdx.x;   // 0 .. NN*64-1
    const int i = t >> 6;
    const int c = t & 63;
    const int h = c >> 3;

    float a = 0.f, den = 0.f;
    #pragma unroll
    for (int s = 0; s < SPLITS; s++) {
        a   += pacc_buf[((size_t)s * NN + i) * 64 + c];
        den += psum_buf[((size_t)s * NN + i) * 8 + h];
    }
    const float v = a / den;
    out[t] = (v >= 0.f) ? v : expm1f(v);
}

// ---------------- launch ----------------
extern "C" void kernel_launch(void* const* d_in, const int* in_sizes, int n_in,
                              void* d_out, int out_size)
{
    const float* vert = (const float*)d_in[0];   // [4096,1433]
    const int*   edge = (const int*)  d_in[1];   // [4096,4096]
    const float* W    = (const float*)d_in[2];   // [1433,64]
    const float* a_l  = (const float*)d_in[3];   // [8,8]
    const float* a_r  = (const float*)d_in[4];   // [8,8]
    float* out = (float*)d_out;                  // [4096,64]

    gemm_proj<<<dim3(NN / GM, KSPL), 128>>>(vert, W);
    prep_scores<<<(NN * NH) / 256, 256>>>(a_l, a_r);
    attn_kernel<<<dim3(SPLITS, NN / TIA), 512>>>(edge);
    combine_kernel<<<(NN * FOUT) / 256, 256>>>(out);
}

// round 10
// speedup vs baseline: 1.0526x; 1.0526x over previous
#include <cuda_runtime.h>
#include <cuda_bf16.h>
#include <math.h>

// Problem constants (fixed shapes)
#define NN      4096      // nodes
#define KIN     1433      // in features
#define NH      8         // heads
#define FOUT    64        // NH*DHD
#define LRELU   0.2f

// Attention tiling (tensor-core version)
#define TIA     64        // i rows per block
#define TJ      64        // j tile in smem
#define SPLITS  16        // j-axis splits
#define CHUNK   (NN / SPLITS)   // 256

// GEMM split-K (128x64 tiles, 128 threads, 8x8 per thread)
#define GM      128
#define KSPL    16
#define KCH     90        // ceil(1433/16)

typedef unsigned long long u64;

// ---------------- scratch (no allocations allowed) ----------------
__device__ __align__(16) float g_buf[NN * FOUT];             // 1 MB
__device__ __align__(16) float2 Lbuf[NN * NH];               // (e^sl, e^{0.2 sl}) packed pair
__device__ __align__(16) float2 Rbuf[NN * NH];               // (e^sr, e^{0.2 sr}) packed pair
__device__ __align__(16) float pacc_buf[SPLITS * NN * FOUT]; // 16 MB (gemm partials then attn partials)
__device__ __align__(16) float psum_buf[SPLITS * NN * NH];   // 2 MB partial denom

// f32x2 packed helpers (Blackwell; PTX-only). "l" constraint = 64-bit int reg.
__device__ __forceinline__ u64 ffma2(u64 a, u64 b, u64 c) {
    u64 d;
    asm("fma.rn.f32x2 %0, %1, %2, %3;" : "=l"(d) : "l"(a), "l"(b), "l"(c));
    return d;
}
__device__ __forceinline__ u64 fmul2(u64 a, u64 b) {
    u64 d;
    asm("mul.rn.f32x2 %0, %1, %2;" : "=l"(d) : "l"(a), "l"(b));
    return d;
}
__device__ __forceinline__ u64 pack2(float lo, float hi) {
    u64 d;
    asm("mov.b64 %0, {%1, %2};" : "=l"(d) : "f"(lo), "f"(hi));
    return d;
}
__device__ __forceinline__ void unpack2(u64 d, float& lo, float& hi) {
    asm("mov.b64 {%0, %1}, %2;" : "=f"(lo), "=f"(hi) : "l"(d));
}
__device__ __forceinline__ unsigned int tf32_rna(float f) {
    unsigned int r;
    asm("cvt.rna.tf32.f32 %0, %1;" : "=r"(r) : "f"(f));
    return r;
}
// w = tf32-truncate((max of both lrelu branches) masked by mu) — ONE 3-input LOP3.
// HMMA truncates tf32 inputs, so this w is bit-identical to what the mma consumes;
// summing the same w in fp32 makes numerator/denominator cancellation exact.
__device__ __forceinline__ float wmax(u64 eifi, u64 ef, unsigned int mu) {
    const u64 p = fmul2(eifi, ef);
    float lo, hi; unpack2(p, lo, hi);
    const float mx = fmaxf(lo, hi);                                     // FMNMX (alu)
    return __uint_as_float(__float_as_uint(mx) & mu & 0xFFFFE000u);     // LOP3 (alu)
}
// tf32 mma: D += A(16x8) * B(8x8), A values already truncated to tf32 grid
__device__ __forceinline__ void mma_tf32(float* d, float a0, float a1, float a2, float a3,
                                         unsigned int b0, unsigned int b1) {
    asm volatile(
        "mma.sync.aligned.m16n8k8.row.col.f32.tf32.tf32.f32 "
        "{%0,%1,%2,%3}, {%4,%5,%6,%7}, {%8,%9}, {%0,%1,%2,%3};"
        : "+f"(d[0]), "+f"(d[1]), "+f"(d[2]), "+f"(d[3])
        : "r"(__float_as_uint(a0)), "r"(__float_as_uint(a1)),
          "r"(__float_as_uint(a2)), "r"(__float_as_uint(a3)),
          "r"(b0), "r"(b1));
}

// ---------------- Kernel 1: g = vert @ W  (f32x2 GEMM, split-K, 8x8/thread) ----------------
__global__ void __launch_bounds__(128) gemm_proj(const float* __restrict__ A,
                                                 const float* __restrict__ B)
{
    __shared__ u64   Asd[16][132];  // (a,a) dup pairs; EVEN stride -> 16B-aligned rows
    __shared__ float Bs[16][68];
    const int tid = threadIdx.x;
    const int m0  = blockIdx.x * GM;
    const int spl = blockIdx.y;
    const int kb  = spl * KCH;
    const int ke  = min(KIN, kb + KCH);
    const int tx  = tid & 7;
    const int ty  = tid >> 3;

    u64 acc[8][4] = {};

    for (int k0 = kb; k0 < ke; k0 += 16) {
        {
            const int kk  = tid & 15;
            const int rb  = tid >> 4;
            const bool ok = (k0 + kk < ke);
            #pragma unroll
            for (int p = 0; p < 16; p++) {
                const int row = rb + p * 8;
                const float v = ok ? A[(size_t)(m0 + row) * KIN + k0 + kk] : 0.f;
                Asd[kk][row] = pack2(v, v);
            }
        }
        {
            #pragma unroll
            for (int p = 0; p < 2; p++) {
                const int i4 = tid + p * 128;
                const int rr = i4 >> 4;
                const int c4 = i4 & 15;
                float4 v = make_float4(0.f, 0.f, 0.f, 0.f);
                if (k0 + rr < ke) v = *(const float4*)&B[(size_t)(k0 + rr) * 64 + c4 * 4];
                *(float4*)&Bs[rr][c4 * 4] = v;
            }
        }
        __syncthreads();

        #pragma unroll
        for (int kk = 0; kk < 16; kk++) {
            ulonglong2 a01 = *(const ulonglong2*)&Asd[kk][ty * 8 + 0];
            ulonglong2 a23 = *(const ulonglong2*)&Asd[kk][ty * 8 + 2];
            ulonglong2 a45 = *(const ulonglong2*)&Asd[kk][ty * 8 + 4];
            ulonglong2 a67 = *(const ulonglong2*)&Asd[kk][ty * 8 + 6];
            ulonglong2 b01 = *(const ulonglong2*)&Bs[kk][tx * 8 + 0];
            ulonglong2 b23 = *(const ulonglong2*)&Bs[kk][tx * 8 + 4];
            u64 ar[8] = {a01.x, a01.y, a23.x, a23.y, a45.x, a45.y, a67.x, a67.y};
            #pragma unroll
            for (int r = 0; r < 8; r++) {
                acc[r][0] = ffma2(ar[r], b01.x, acc[r][0]);
                acc[r][1] = ffma2(ar[r], b01.y, acc[r][1]);
                acc[r][2] = ffma2(ar[r], b23.x, acc[r][2]);
                acc[r][3] = ffma2(ar[r], b23.y, acc[r][3]);
            }
        }
        __syncthreads();
    }

    #pragma unroll
    for (int r = 0; r < 8; r++) {
        float x0, x1, x2, x3, x4, x5, x6, x7;
        unpack2(acc[r][0], x0, x1);
        unpack2(acc[r][1], x2, x3);
        unpack2(acc[r][2], x4, x5);
        unpack2(acc[r][3], x6, x7);
        float* p = &pacc_buf[((size_t)spl * NN + m0 + ty * 8 + r) * 64 + tx * 8];
        *(float4*)(p + 0) = make_float4(x0, x1, x2, x3);
        *(float4*)(p + 4) = make_float4(x4, x5, x6, x7);
    }
}

// ---------------- Kernel 2: reduce split-K + per-(node,head) factored exps ----------------
__global__ void __launch_bounds__(256) prep_scores(const float* __restrict__ a_l,
                                                   const float* __restrict__ a_r)
{
    const int t = blockIdx.x * blockDim.x + threadIdx.x;
    const int n = t >> 3;
    const int h = t & 7;

    float4 s0 = make_float4(0.f, 0.f, 0.f, 0.f);
    float4 s1 = s0;
    #pragma unroll
    for (int s = 0; s < KSPL; s++) {
        const float* p = &pacc_buf[((size_t)s * NN + n) * 64 + h * 8];
        const float4 p0 = *(const float4*)(p + 0);
        const float4 p1 = *(const float4*)(p + 4);
        s0.x += p0.x; s0.y += p0.y; s0.z += p0.z; s0.w += p0.w;
        s1.x += p1.x; s1.y += p1.y; s1.z += p1.z; s1.w += p1.w;
    }
    *(float4*)&g_buf[(size_t)n * 64 + h * 8 + 0] = s0;
    *(float4*)&g_buf[(size_t)n * 64 + h * 8 + 4] = s1;

    const float4 al0 = *(const float4*)&a_l[h * 8 + 0];
    const float4 al1 = *(const float4*)&a_l[h * 8 + 4];
    const float4 ar0 = *(const float4*)&a_r[h * 8 + 0];
    const float4 ar1 = *(const float4*)&a_r[h * 8 + 4];

    const float sl = s0.x*al0.x + s0.y*al0.y + s0.z*al0.z + s0.w*al0.w
                   + s1.x*al1.x + s1.y*al1.y + s1.z*al1.z + s1.w*al1.w;
    const float sr = s0.x*ar0.x + s0.y*ar0.y + s0.z*ar0.z + s0.w*ar0.w
                   + s1.x*ar1.x + s1.y*ar1.y + s1.z*ar1.z + s1.w*ar1.w;

    Lbuf[t] = make_float2(expf(sl), expf(LRELU * sl));
    Rbuf[t] = make_float2(expf(sr), expf(LRELU * sr));
}

// ---------------- Kernel 3: masked softmax-aggregation via tf32 mma ----------------
// 256 thr = 8 warps; warp = 16 rows x 4 heads (max ILP per chain). 3 blocks/SM.
__global__ void __launch_bounds__(256, 3) attn_kernel(const int* __restrict__ edge)
{
    __shared__ u64 gp[8][64][4];           // 16 KB: (tf32 G[j4], tf32 G[j4+4]) pairs
    __shared__ u64 rsu[TJ * 8];            // 4 KB: (e^sr, e^{.2 sr}) per (j,h)
    __shared__ unsigned int msk[TIA][68];  // 17 KB: 0xFFFFFFFF/0 per (i,j)

    const int tid  = threadIdx.x;
    const int lane = tid & 31;
    const int wrp  = tid >> 5;
    const int gid  = lane >> 2;     // fragment row 0..7
    const int tig  = lane & 3;      // fragment col/k group
    const int rw   = (wrp & 3) * 16;
    const int hb   = (wrp >> 2) * 4;
    const int split = blockIdx.x;
    const int i0   = blockIdx.y * TIA;
    const int j0   = split * CHUNK;

    const u64* Lu = (const u64*)Lbuf;
    const u64* Ru = (const u64*)Rbuf;

    u64 EiF[4][2];
    #pragma unroll
    for (int hh = 0; hh < 4; hh++) {
        EiF[hh][0] = Lu[(size_t)(i0 + rw + gid) * 8 + hb + hh];
        EiF[hh][1] = Lu[(size_t)(i0 + rw + gid + 8) * 8 + hb + hh];
    }

    float accG[4][4] = {};            // O fragments per head
    float sL0[4] = {}, sL1[4] = {};   // denominator partial sums (rows gid, gid+8)

    const int4* e4 = (const int4*)edge;

    for (int jt = 0; jt < CHUNK; jt += TJ) {
        const int jb = j0 + jt;
        __syncthreads();

        // stage G pairs (rna tf32): each g row converted exactly once
        #pragma unroll
        for (int k = 0; k < 8; k++) {
            const int idx = tid + k * 256;
            const int hd  = (idx >> 2) & 63;
            const int j4  = idx & 3;
            const int j8  = idx >> 8;
            const int jr  = jb + j8 * 8 + j4;
            const unsigned int lo = tf32_rna(g_buf[(size_t)jr * 64 + hd]);
            const unsigned int hi = tf32_rna(g_buf[(size_t)(jr + 4) * 64 + hd]);
            gp[j8][hd][j4] = ((u64)hi << 32) | lo;
        }
        // stage EF
        #pragma unroll
        for (int k = 0; k < 2; k++) {
            const int idx = tid + k * 256;
            rsu[idx] = Ru[(size_t)(jb + (idx >> 3)) * 8 + (idx & 7)];
        }
        // stage mask words (0xFFFFFFFF / 0)
        #pragma unroll
        for (int k = 0; k < 4; k++) {
            const int idx = tid + k * 256;
            const int ii  = idx >> 4;
            const int jq  = idx & 15;
            const int4 v  = e4[(size_t)(i0 + ii) * (NN / 4) + (jb >> 2) + jq];
            uint4 f;
            f.x = (v.x != 0) ? 0xFFFFFFFFu : 0u;
            f.y = (v.y != 0) ? 0xFFFFFFFFu : 0u;
            f.z = (v.z != 0) ? 0xFFFFFFFFu : 0u;
            f.w = (v.w != 0) ? 0xFFFFFFFFu : 0u;
            *(uint4*)&msk[ii][jq * 4] = f;
        }
        __syncthreads();

        #pragma unroll 2
        for (int j8 = 0; j8 < 8; j8++) {
            const unsigned int mu0 = msk[rw + gid][j8 * 8 + tig];
            const unsigned int mu1 = msk[rw + gid + 8][j8 * 8 + tig];
            const unsigned int mu2 = msk[rw + gid][j8 * 8 + tig + 4];
            const unsigned int mu3 = msk[rw + gid + 8][j8 * 8 + tig + 4];
            // EF for head quad hb..hb+3 (adjacent u64s) -> LDS128 pairs
            const ulonglong2 e0a = *(const ulonglong2*)&rsu[(j8 * 8 + tig) * 8 + hb];
            const ulonglong2 e0b = *(const ulonglong2*)&rsu[(j8 * 8 + tig) * 8 + hb + 2];
            const ulonglong2 e1a = *(const ulonglong2*)&rsu[(j8 * 8 + tig + 4) * 8 + hb];
            const ulonglong2 e1b = *(const ulonglong2*)&rsu[(j8 * 8 + tig + 4) * 8 + hb + 2];
            const u64 EF0[4] = {e0a.x, e0a.y, e0b.x, e0b.y};
            const u64 EF1[4] = {e1a.x, e1a.y, e1b.x, e1b.y};
            #pragma unroll
            for (int hh = 0; hh < 4; hh++) {
                const int h = hb + hh;
                const float a0 = wmax(EiF[hh][0], EF0[hh], mu0);
                const float a1 = wmax(EiF[hh][1], EF0[hh], mu1);
                const float a2 = wmax(EiF[hh][0], EF1[hh], mu2);
                const float a3 = wmax(EiF[hh][1], EF1[hh], mu3);
                sL0[hh] += a0 + a2;
                sL1[hh] += a1 + a3;
                const uint2 b = *(const uint2*)&gp[j8][h * 8 + gid][tig];
                mma_tf32(accG[hh], a0, a1, a2, a3, b.x, b.y);
            }
        }
    }

    // epilogue: reduce denominators over the 4-lane tig group, write partials
    #pragma unroll
    for (int hh = 0; hh < 4; hh++) {
        float s0 = sL0[hh], s1 = sL1[hh];
        s0 += __shfl_xor_sync(0xFFFFFFFFu, s0, 1);
        s0 += __shfl_xor_sync(0xFFFFFFFFu, s0, 2);
        s1 += __shfl_xor_sync(0xFFFFFFFFu, s1, 1);
        s1 += __shfl_xor_sync(0xFFFFFFFFu, s1, 2);

        const int h = hb + hh;
        const int ir0 = i0 + rw + gid;
        const int ir1 = ir0 + 8;
        float* p0 = &pacc_buf[((size_t)split * NN + ir0) * 64 + h * 8 + tig * 2];
        float* p1 = &pacc_buf[((size_t)split * NN + ir1) * 64 + h * 8 + tig * 2];
        *(float2*)p0 = make_float2(accG[hh][0], accG[hh][1]);
        *(float2*)p1 = make_float2(accG[hh][2], accG[hh][3]);
        if (tig == 0) {
            psum_buf[((size_t)split * NN + ir0) * 8 + h] = s0;
            psum_buf[((size_t)split * NN + ir1) * 8 + h] = s1;
        }
    }
}

// ---------------- Kernel 4: combine splits, normalize, ELU ----------------
__global__ void __launch_bounds__(256) combine_kernel(float* __restrict__ out)
{
    const int t = blockIdx.x * blockDim.x + threadIdx.x;   // 0 .. NN*64-1
    const int i = t >> 6;
    const int c = t & 63;
    const int h = c >> 3;

    float a = 0.f, den = 0.f;
    #pragma unroll
    for (int s = 0; s < SPLITS; s++) {
        a   += pacc_buf[((size_t)s * NN + i) * 64 + c];
        den += psum_buf[((size_t)s * NN + i) * 8 + h];
    }
    const float v = a / den;
    out[t] = (v >= 0.f) ? v : expm1f(v);
}

// ---------------- launch ----------------
extern "C" void kernel_launch(void* const* d_in, const int* in_sizes, int n_in,
                              void* d_out, int out_size)
{
    const float* vert = (const float*)d_in[0];   // [4096,1433]
    const int*   edge = (const int*)  d_in[1];   // [4096,4096]
    const float* W    = (const float*)d_in[2];   // [1433,64]
    const float* a_l  = (const float*)d_in[3];   // [8,8]
    const float* a_r  = (const float*)d_in[4];   // [8,8]
    float* out = (float*)d_out;                  // [4096,64]

    gemm_proj<<<dim3(NN / GM, KSPL), 128>>>(vert, W);
    prep_scores<<<(NN * NH) / 256, 256>>>(a_l, a_r);
    attn_kernel<<<dim3(SPLITS, NN / TIA), 256>>>(edge);
    combine_kernel<<<(NN * FOUT) / 256, 256>>>(out);
}